// round 2
// baseline (speedup 1.0000x reference)
#include <cuda_runtime.h>

#define NROWS 8192
#define DIM   512
#define TILE  128
#define BK    16

// Scratch (allocation-free rule: __device__ globals)
__device__ float g_e[NROWS * DIM];   // normalized embeddings, 16 MB
__device__ float g_num[NROWS];
__device__ float g_den[NROWS];
__device__ int   g_lab[NROWS];       // decoded int32 labels

// ---------------------------------------------------------------------------
// Kernel 0: decode labels. Handles both int32 and int64 on-disk layouts.
// int64 layout (little-endian, values < 512): high word of every element is 0,
// i.e. odd int32 indices are all zero. Genuine int32 labels: odd indices are
// random in [0,512) -> nonzero with p=511/512 each; over 4096 samples the
// all-zero case is impossible.
// ---------------------------------------------------------------------------
__global__ void decode_labels_kernel(const int* __restrict__ lab32, int n) {
    __shared__ int odd_nonzero;
    if (threadIdx.x == 0) odd_nonzero = 0;
    __syncthreads();
    // Inspect odd int32 words of the first n/2 logical entries — indices
    // 2*i+1 < n, in-bounds under BOTH interpretations.
    for (int i = threadIdx.x; i < n / 2; i += blockDim.x)
        if (lab32[2 * i + 1] != 0) odd_nonzero = 1;   // benign race, any write sets it
    __syncthreads();
    const bool is64 = (odd_nonzero == 0);
    for (int i = threadIdx.x; i < n; i += blockDim.x)
        g_lab[i] = is64 ? lab32[2 * i] : lab32[i];
}

// ---------------------------------------------------------------------------
// Kernel 1: L2-normalize each row; also zero the per-row accumulators.
// ---------------------------------------------------------------------------
__global__ void normalize_kernel(const float* __restrict__ emb) {
    const int row = blockIdx.x;
    const float* in = emb + (size_t)row * DIM;
    float* out = g_e + (size_t)row * DIM;

    const int c = threadIdx.x * 4;       // 128 threads * 4 = 512 = DIM
    float4 x = *(const float4*)(in + c);
    float ss = x.x * x.x + x.y * x.y + x.z * x.z + x.w * x.w;

    #pragma unroll
    for (int o = 16; o; o >>= 1) ss += __shfl_xor_sync(0xffffffffu, ss, o);

    __shared__ float red[4];
    if ((threadIdx.x & 31) == 0) red[threadIdx.x >> 5] = ss;
    __syncthreads();
    const float tot = red[0] + red[1] + red[2] + red[3];
    const float inv = 1.0f / sqrtf(tot);

    float4 y;
    y.x = x.x * inv; y.y = x.y * inv; y.z = x.z * inv; y.w = x.w * inv;
    *(float4*)(out + c) = y;

    if (threadIdx.x == 0) { g_num[row] = 0.0f; g_den[row] = 0.0f; }
}

// ---------------------------------------------------------------------------
// Kernel 2: fused sim-GEMM + exp + mask + per-row num/den accumulation.
// 128x128 output tile per block, 256 threads, 8x8 accumulator per thread.
// ---------------------------------------------------------------------------
__global__ __launch_bounds__(256) void sim_loss_kernel() {
    __shared__ float As[BK][TILE + 4];
    __shared__ float Bs[BK][TILE + 4];
    __shared__ int   labR[TILE];
    __shared__ int   labC[TILE];

    const int tid = threadIdx.x;
    const int tx = tid & 15;            // 0..15 -> column group
    const int ty = tid >> 4;            // 0..15 -> row group
    const int rowBase = blockIdx.y * TILE;
    const int colBase = blockIdx.x * TILE;

    if (tid < TILE) {
        labR[tid] = g_lab[rowBase + tid];
        labC[tid] = g_lab[colBase + tid];
    }

    float acc[8][8];
    #pragma unroll
    for (int i = 0; i < 8; i++)
        #pragma unroll
        for (int j = 0; j < 8; j++) acc[i][j] = 0.0f;

    const float* Ag = g_e + (size_t)rowBase * DIM;
    const float* Bg = g_e + (size_t)colBase * DIM;

    for (int k0 = 0; k0 < DIM; k0 += BK) {
        #pragma unroll
        for (int l = 0; l < 2; l++) {
            const int idx = tid + l * 256;        // 0..511
            const int r  = idx >> 2;              // 0..127  (tile row)
            const int kq = (idx & 3) << 2;        // 0,4,8,12 (k sub-offset)
            float4 a = *(const float4*)(Ag + (size_t)r * DIM + k0 + kq);
            As[kq + 0][r] = a.x; As[kq + 1][r] = a.y;
            As[kq + 2][r] = a.z; As[kq + 3][r] = a.w;
            float4 b = *(const float4*)(Bg + (size_t)r * DIM + k0 + kq);
            Bs[kq + 0][r] = b.x; Bs[kq + 1][r] = b.y;
            Bs[kq + 2][r] = b.z; Bs[kq + 3][r] = b.w;
        }
        __syncthreads();

        #pragma unroll
        for (int k = 0; k < BK; k++) {
            float ar[8], br[8];
            *(float4*)&ar[0] = *(const float4*)&As[k][ty * 8];
            *(float4*)&ar[4] = *(const float4*)&As[k][ty * 8 + 4];
            *(float4*)&br[0] = *(const float4*)&Bs[k][tx * 8];
            *(float4*)&br[4] = *(const float4*)&Bs[k][tx * 8 + 4];
            #pragma unroll
            for (int i = 0; i < 8; i++)
                #pragma unroll
                for (int j = 0; j < 8; j++)
                    acc[i][j] += ar[i] * br[j];
        }
        __syncthreads();
    }

    // Epilogue: sim = acc/T, exp, masks, per-row partial sums
    const float INVT = 14.285714285714286f;   // 1/0.07
    float num[8], den[8];
    #pragma unroll
    for (int i = 0; i < 8; i++) { num[i] = 0.0f; den[i] = 0.0f; }

    #pragma unroll
    for (int i = 0; i < 8; i++) {
        const int gi = rowBase + ty * 8 + i;
        const int li = labR[ty * 8 + i];
        #pragma unroll
        for (int j = 0; j < 8; j++) {
            const int gj = colBase + tx * 8 + j;
            const float s = acc[i][j] * INVT;
            const float e = __expf(s);
            if (gi != gj) {
                den[i] += e;
                if (li == labC[tx * 8 + j] && s > 0.0f) num[i] += e;
            }
        }
    }

    // Reduce across the 16 lanes sharing the same rows (tx dimension)
    #pragma unroll
    for (int i = 0; i < 8; i++) {
        #pragma unroll
        for (int o = 8; o; o >>= 1) {
            num[i] += __shfl_xor_sync(0xffffffffu, num[i], o);
            den[i] += __shfl_xor_sync(0xffffffffu, den[i], o);
        }
    }
    if (tx == 0) {
        #pragma unroll
        for (int i = 0; i < 8; i++) {
            atomicAdd(&g_num[rowBase + ty * 8 + i], num[i]);
            atomicAdd(&g_den[rowBase + ty * 8 + i], den[i]);
        }
    }
}

// ---------------------------------------------------------------------------
// Kernel 3: per-row loss, valid-row mean, abs -> scalar output
// ---------------------------------------------------------------------------
__global__ void finalize_kernel(float* __restrict__ out) {
    float sum = 0.0f;
    int cnt = 0;
    for (int i = threadIdx.x; i < NROWS; i += 256) {
        const float nu = g_num[i];
        const float de = g_den[i];
        if (nu > 0.0f && de > 0.0f) {
            // loss_i = -log(num/(den+eps)) = log((den+eps)/num)
            sum += logf((de + 1e-8f) / nu);
            cnt++;
        }
    }
    #pragma unroll
    for (int o = 16; o; o >>= 1) {
        sum += __shfl_xor_sync(0xffffffffu, sum, o);
        cnt += __shfl_xor_sync(0xffffffffu, cnt, o);
    }
    __shared__ float ssum[8];
    __shared__ int   scnt[8];
    if ((threadIdx.x & 31) == 0) {
        ssum[threadIdx.x >> 5] = sum;
        scnt[threadIdx.x >> 5] = cnt;
    }
    __syncthreads();
    if (threadIdx.x == 0) {
        float s = 0.0f; int c = 0;
        #pragma unroll
        for (int i = 0; i < 8; i++) { s += ssum[i]; c += scnt[i]; }
        out[0] = (c > 0) ? fabsf(s / (float)c) : 0.0f;
    }
}

extern "C" void kernel_launch(void* const* d_in, const int* in_sizes, int n_in,
                              void* d_out, int out_size) {
    const float* emb = (const float*)d_in[0];
    const int* lab32 = (const int*)d_in[1];
    float* out = (float*)d_out;

    decode_labels_kernel<<<1, 256>>>(lab32, NROWS);
    normalize_kernel<<<NROWS, 128>>>(emb);
    dim3 grid(NROWS / TILE, NROWS / TILE);   // 64 x 64 blocks
    sim_loss_kernel<<<grid, 256>>>();
    finalize_kernel<<<1, 256>>>(out);
}

// round 4
// speedup vs baseline: 4.4067x; 4.4067x over previous
#include <cuda_runtime.h>
#include <cuda_bf16.h>
#include <cstdint>

#define NROWS 8192
#define DIM   512
#define TM    128
#define TN    128
#define KC    32              // K chunk (bf16 elems): 64 B per row
#define NC    (DIM / KC)      // 16 chunks
#define NBLK  (NROWS / TM)    // 64
#define PITCH 80              // smem row pitch bytes (64B data + 16B pad; 16B-aligned, 5 ⊥ 8)

#define INVT_LOG2E 20.609929155556620f   // log2(e)/0.07

// ---- scratch (__device__ globals; allocation-free rule) ----
__device__ __nv_bfloat16 g_ebf[NROWS * DIM];   // normalized embeddings, bf16, 8 MB
__device__ float g_num[NROWS];
__device__ float g_den[NROWS];
__device__ int   g_lab[NROWS];

// ---- static smem layout (bytes) ----
#define OFF_A0   0
#define OFF_B0   10240
#define OFF_A1   20480
#define OFF_B1   30720
#define OFF_LABR 40960
#define OFF_LABC 41472
#define OFF_RN   41984
#define OFF_RD   42496
#define OFF_CN   43008
#define OFF_CD   43520
#define SM_TOTAL 44032

// ============================ PTX helpers ============================
__device__ __forceinline__ uint32_t smem_u32(const void* p) {
    uint32_t a;
    asm("{ .reg .u64 t; cvta.to.shared.u64 t, %1; cvt.u32.u64 %0, t; }" : "=r"(a) : "l"(p));
    return a;
}
#define CPA(dst, src)  asm volatile("cp.async.cg.shared.global [%0], [%1], 16;" :: "r"(dst), "l"(src))
#define CPA_COMMIT()   asm volatile("cp.async.commit_group;" ::: "memory")
#define CPA_WAIT(n)    asm volatile("cp.async.wait_group %0;" :: "n"(n) : "memory")

__device__ __forceinline__ void ldmx4(uint32_t& r0, uint32_t& r1, uint32_t& r2, uint32_t& r3,
                                      uint32_t addr) {
    asm volatile("ldmatrix.sync.aligned.m8n8.x4.shared.b16 {%0,%1,%2,%3}, [%4];"
                 : "=r"(r0), "=r"(r1), "=r"(r2), "=r"(r3) : "r"(addr));
}
__device__ __forceinline__ void mma16816(float* d, const uint32_t* a, const uint32_t* b) {
    asm volatile(
        "mma.sync.aligned.m16n8k16.row.col.f32.bf16.bf16.f32 "
        "{%0,%1,%2,%3}, {%4,%5,%6,%7}, {%8,%9}, {%0,%1,%2,%3};"
        : "+f"(d[0]), "+f"(d[1]), "+f"(d[2]), "+f"(d[3])
        : "r"(a[0]), "r"(a[1]), "r"(a[2]), "r"(a[3]), "r"(b[0]), "r"(b[1]));
}
__device__ __forceinline__ float fast_exp2(float x) {
    float y;
    asm("ex2.approx.f32 %0, %1;" : "=f"(y) : "f"(x));
    return y;
}

// ============================ Kernel 0: decode labels ============================
// Handles int64-on-disk (odd int32 words all zero) vs genuine int32 labels.
__global__ void decode_labels_kernel(const int* __restrict__ lab32, int n) {
    __shared__ int odd_nonzero;
    if (threadIdx.x == 0) odd_nonzero = 0;
    __syncthreads();
    for (int i = threadIdx.x; i < n / 2; i += blockDim.x)
        if (lab32[2 * i + 1] != 0) odd_nonzero = 1;
    __syncthreads();
    const bool is64 = (odd_nonzero == 0);
    for (int i = threadIdx.x; i < n; i += blockDim.x)
        g_lab[i] = is64 ? lab32[2 * i] : lab32[i];
}

// ============================ Kernel 1: normalize -> bf16 ============================
__global__ void normalize_kernel(const float* __restrict__ emb) {
    const int row = blockIdx.x;
    const float* in = emb + (size_t)row * DIM;

    const int c = threadIdx.x * 4;       // 128 threads * 4 = 512
    float4 x = *(const float4*)(in + c);
    float ss = x.x * x.x + x.y * x.y + x.z * x.z + x.w * x.w;

    #pragma unroll
    for (int o = 16; o; o >>= 1) ss += __shfl_xor_sync(0xffffffffu, ss, o);

    __shared__ float red[4];
    if ((threadIdx.x & 31) == 0) red[threadIdx.x >> 5] = ss;
    __syncthreads();
    const float inv = rsqrtf(red[0] + red[1] + red[2] + red[3]);

    __nv_bfloat162 p0 = __floats2bfloat162_rn(x.x * inv, x.y * inv);
    __nv_bfloat162 p1 = __floats2bfloat162_rn(x.z * inv, x.w * inv);
    __nv_bfloat162* out = (__nv_bfloat162*)(g_ebf + (size_t)row * DIM + c);
    out[0] = p0; out[1] = p1;

    if (threadIdx.x == 0) { g_num[row] = 0.0f; g_den[row] = 0.0f; }
}

// ============================ Kernel 2: mma.sync GEMM + fused epilogue ============================
__global__ __launch_bounds__(256)
void sim_loss_mma() {
    __shared__ __align__(128) char SM[SM_TOTAL];
    const uint32_t sbase = smem_u32(SM);
    const int tid = threadIdx.x, wid = tid >> 5, lane = tid & 31;
    const int wm = wid >> 2, wn = wid & 3;   // warp grid 2 (M) x 4 (N)

    // Linear block id -> upper-triangle tile (bi <= bj)
    int t = blockIdx.x, bi = 0;
    while (t >= NBLK - bi) { t -= NBLK - bi; bi++; }
    const int bj = bi + t;
    const int rowBase = bi * TM, colBase = bj * TN;
    const bool offDiag = (bi != bj);

    int*   labR = (int*)(SM + OFF_LABR);
    int*   labC = (int*)(SM + OFF_LABC);
    float* sRN  = (float*)(SM + OFF_RN);
    float* sRD  = (float*)(SM + OFF_RD);
    float* sCN  = (float*)(SM + OFF_CN);
    float* sCD  = (float*)(SM + OFF_CD);

    if (tid < 128) {
        labR[tid] = g_lab[rowBase + tid];
        labC[tid] = g_lab[colBase + tid];
        sRN[tid] = 0.0f; sRD[tid] = 0.0f;
    } else {
        sCN[tid - 128] = 0.0f; sCD[tid - 128] = 0.0f;
    }

    const __nv_bfloat16* Ag = g_ebf + (size_t)rowBase * DIM;
    const __nv_bfloat16* Bg = g_ebf + (size_t)colBase * DIM;

    float acc[4][4][4];
    #pragma unroll
    for (int i = 0; i < 4; i++)
        #pragma unroll
        for (int j = 0; j < 4; j++)
            #pragma unroll
            for (int v = 0; v < 4; v++) acc[i][j][v] = 0.0f;

    // ---- prefetch chunk 0 ----
    {
        const uint32_t sa = sbase + OFF_A0, sb = sbase + OFF_B0;
        #pragma unroll
        for (int i = 0; i < 2; i++) {
            const int seg = tid + i * 256;        // 0..511
            const int r = seg >> 2, s = seg & 3;
            CPA(sa + r * PITCH + s * 16, Ag + (size_t)r * DIM + s * 8);
            CPA(sb + r * PITCH + s * 16, Bg + (size_t)r * DIM + s * 8);
        }
        CPA_COMMIT();
    }

    for (int c = 0; c < NC; c++) {
        if (c + 1 < NC) {   // prefetch next chunk into the other buffer
            const int k0 = (c + 1) * KC;
            const uint32_t sa = sbase + (((c + 1) & 1) ? OFF_A1 : OFF_A0);
            const uint32_t sb = sbase + (((c + 1) & 1) ? OFF_B1 : OFF_B0);
            #pragma unroll
            for (int i = 0; i < 2; i++) {
                const int seg = tid + i * 256;
                const int r = seg >> 2, s = seg & 3;
                CPA(sa + r * PITCH + s * 16, Ag + (size_t)r * DIM + k0 + s * 8);
                CPA(sb + r * PITCH + s * 16, Bg + (size_t)r * DIM + k0 + s * 8);
            }
            CPA_COMMIT();
            CPA_WAIT(1);    // chunk c has landed
        } else {
            CPA_WAIT(0);
        }
        __syncthreads();

        const uint32_t sa = sbase + ((c & 1) ? OFF_A1 : OFF_A0);
        const uint32_t sb = sbase + ((c & 1) ? OFF_B1 : OFF_B0);

        #pragma unroll
        for (int ks = 0; ks < 2; ks++) {          // two k16 steps per 32-chunk
            // B fragments: 2 x ldmatrix.x4 covering 4 n-tiles
            uint32_t bfr[4][2];
            #pragma unroll
            for (int p = 0; p < 2; p++) {
                const int nrow = wn * 32 + p * 16 + ((lane >> 4) << 3) + (lane & 7);
                const int koff = ks * 32 + ((lane >> 3) & 1) * 16;
                uint32_t r0, r1, r2, r3;
                ldmx4(r0, r1, r2, r3, sb + nrow * PITCH + koff);
                bfr[2 * p][0] = r0; bfr[2 * p][1] = r1;
                bfr[2 * p + 1][0] = r2; bfr[2 * p + 1][1] = r3;
            }
            #pragma unroll
            for (int mt = 0; mt < 4; mt++) {
                const int arow = wm * 64 + mt * 16 + (lane & 15);
                const int akoff = ks * 32 + (lane >> 4) * 16;
                uint32_t afr[4];
                ldmx4(afr[0], afr[1], afr[2], afr[3], sa + arow * PITCH + akoff);
                #pragma unroll
                for (int nt = 0; nt < 4; nt++)
                    mma16816(acc[mt][nt], afr, bfr[nt]);
            }
        }
        __syncthreads();   // all reads done before next prefetch overwrites
    }

    // ---- fused epilogue ----
    // Thread t owns rows {wm*64 + mt*16 + rh*8 + t/4} and cols {wn*32 + nt*8 + 2*(t%4)+ce}
    #pragma unroll
    for (int mt = 0; mt < 4; mt++) {
        #pragma unroll
        for (int rh = 0; rh < 2; rh++) {
            const int rloc = wm * 64 + mt * 16 + rh * 8 + (lane >> 2);
            const int gi = rowBase + rloc;
            const int li = labR[rloc];
            float rnum = 0.0f, rden = 0.0f;
            #pragma unroll
            for (int nt = 0; nt < 4; nt++) {
                #pragma unroll
                for (int ce = 0; ce < 2; ce++) {
                    const int cloc = wn * 32 + nt * 8 + 2 * (lane & 3) + ce;
                    const int gj = colBase + cloc;
                    const float v = acc[mt][nt][rh * 2 + ce];
                    const float e = fast_exp2(v * INVT_LOG2E);
                    const bool diag = (gi == gj);
                    const bool pos = !diag && (li == labC[cloc]) && (v > 0.0f);
                    rden += diag ? 0.0f : e;
                    rnum += pos ? e : 0.0f;
                }
            }
            atomicAdd(&sRD[rloc], rden);
            if (rnum != 0.0f) atomicAdd(&sRN[rloc], rnum);
        }
    }
    if (offDiag) {   // symmetric contributions to the column rows
        #pragma unroll
        for (int nt = 0; nt < 4; nt++) {
            #pragma unroll
            for (int ce = 0; ce < 2; ce++) {
                const int cloc = wn * 32 + nt * 8 + 2 * (lane & 3) + ce;
                const int lj = labC[cloc];
                float cnum = 0.0f, cden = 0.0f;
                #pragma unroll
                for (int mt = 0; mt < 4; mt++) {
                    #pragma unroll
                    for (int rh = 0; rh < 2; rh++) {
                        const int rloc = wm * 64 + mt * 16 + rh * 8 + (lane >> 2);
                        const float v = acc[mt][nt][rh * 2 + ce];
                        const float e = fast_exp2(v * INVT_LOG2E);
                        const bool pos = (labR[rloc] == lj) && (v > 0.0f);
                        cden += e;
                        cnum += pos ? e : 0.0f;
                    }
                }
                atomicAdd(&sCD[cloc], cden);
                if (cnum != 0.0f) atomicAdd(&sCN[cloc], cnum);
            }
        }
    }
    __syncthreads();

    // flush tile accumulators to global
    if (tid < 128) {
        atomicAdd(&g_den[rowBase + tid], sRD[tid]);
        const float rn = sRN[tid];
        if (rn != 0.0f) atomicAdd(&g_num[rowBase + tid], rn);
    } else if (offDiag) {
        const int i = tid - 128;
        atomicAdd(&g_den[colBase + i], sCD[i]);
        const float cn = sCN[i];
        if (cn != 0.0f) atomicAdd(&g_num[colBase + i], cn);
    }
}

// ============================ Kernel 3: finalize ============================
__global__ void finalize_kernel(float* __restrict__ out) {
    float sum = 0.0f;
    int cnt = 0;
    for (int i = threadIdx.x; i < NROWS; i += 256) {
        const float nu = g_num[i];
        const float de = g_den[i];
        if (nu > 0.0f && de > 0.0f) {
            sum += logf((de + 1e-8f) / nu);
            cnt++;
        }
    }
    #pragma unroll
    for (int o = 16; o; o >>= 1) {
        sum += __shfl_xor_sync(0xffffffffu, sum, o);
        cnt += __shfl_xor_sync(0xffffffffu, cnt, o);
    }
    __shared__ float ssum[8];
    __shared__ int   scnt[8];
    if ((threadIdx.x & 31) == 0) {
        ssum[threadIdx.x >> 5] = sum;
        scnt[threadIdx.x >> 5] = cnt;
    }
    __syncthreads();
    if (threadIdx.x == 0) {
        float s = 0.0f; int c = 0;
        #pragma unroll
        for (int i = 0; i < 8; i++) { s += ssum[i]; c += scnt[i]; }
        out[0] = (c > 0) ? fabsf(s / (float)c) : 0.0f;
    }
}

extern "C" void kernel_launch(void* const* d_in, const int* in_sizes, int n_in,
                              void* d_out, int out_size) {
    const float* emb = (const float*)d_in[0];
    const int* lab32 = (const int*)d_in[1];
    float* out = (float*)d_out;

    decode_labels_kernel<<<1, 256>>>(lab32, NROWS);
    normalize_kernel<<<NROWS, 128>>>(emb);
    const int ntiles = NBLK * (NBLK + 1) / 2;   // 2080 upper-triangle tiles
    sim_loss_mma<<<ntiles, 256>>>();
    finalize_kernel<<<1, 256>>>(out);
}

// round 5
// speedup vs baseline: 6.6289x; 1.5043x over previous
#include <cuda_runtime.h>
#include <cuda_bf16.h>
#include <cstdint>

#define NROWS 8192
#define DIM   512
#define TM    128
#define TN    128
#define KC    32              // K chunk (bf16 elems): 64 B per row
#define NC    (DIM / KC)      // 16 chunks
#define NBLK  (NROWS / TM)    // 64
#define NTILES (NBLK * (NBLK + 1) / 2)   // 2080
#define PITCH 80              // smem row pitch bytes (64B data + 16B pad; conflict-free)
#define STAGES 4
#define STAGE_BYTES 20480     // A (128*80) + B (128*80)

#define INVT_LOG2E 20.609929155556620f   // log2(e)/0.07
#define LN2 0.69314718055994531f

// ---- scratch (__device__ globals; allocation-free rule) ----
__device__ __nv_bfloat16 g_ebf[NROWS * DIM];   // normalized embeddings, bf16, 8 MB
__device__ float g_num[NROWS];
__device__ float g_den[NROWS];
__device__ int   g_lab[NROWS];
__device__ unsigned g_done;                    // grid-completion counter

// ---- dynamic smem layout (bytes) ----
#define OFF_STAGE(s) ((s) * STAGE_BYTES)       // A at +0, B at +10240
#define OFF_LABR (STAGES * STAGE_BYTES)        // 81920
#define OFF_LABC (OFF_LABR + 512)
#define OFF_RN   (OFF_LABC + 512)
#define OFF_RD   (OFF_RN + 512)
#define OFF_CN   (OFF_RD + 512)
#define OFF_CD   (OFF_CN + 512)
#define SMEM_BYTES (OFF_CD + 512)              // 84992

// ============================ PTX helpers ============================
__device__ __forceinline__ uint32_t smem_u32(const void* p) {
    uint32_t a;
    asm("{ .reg .u64 t; cvta.to.shared.u64 t, %1; cvt.u32.u64 %0, t; }" : "=r"(a) : "l"(p));
    return a;
}
#define CPA(dst, src)  asm volatile("cp.async.cg.shared.global [%0], [%1], 16;" :: "r"(dst), "l"(src))
#define CPA_COMMIT()   asm volatile("cp.async.commit_group;" ::: "memory")
#define CPA_WAIT(n)    asm volatile("cp.async.wait_group %0;" :: "n"(n) : "memory")

__device__ __forceinline__ void ldmx4(uint32_t& r0, uint32_t& r1, uint32_t& r2, uint32_t& r3,
                                      uint32_t addr) {
    asm volatile("ldmatrix.sync.aligned.m8n8.x4.shared.b16 {%0,%1,%2,%3}, [%4];"
                 : "=r"(r0), "=r"(r1), "=r"(r2), "=r"(r3) : "r"(addr));
}
__device__ __forceinline__ void mma16816(float* d, const uint32_t* a, const uint32_t* b) {
    asm volatile(
        "mma.sync.aligned.m16n8k16.row.col.f32.bf16.bf16.f32 "
        "{%0,%1,%2,%3}, {%4,%5,%6,%7}, {%8,%9}, {%0,%1,%2,%3};"
        : "+f"(d[0]), "+f"(d[1]), "+f"(d[2]), "+f"(d[3])
        : "r"(a[0]), "r"(a[1]), "r"(a[2]), "r"(a[3]), "r"(b[0]), "r"(b[1]));
}
__device__ __forceinline__ float fast_exp2(float x) {
    float y;
    asm("ex2.approx.f32 %0, %1;" : "=f"(y) : "f"(x));
    return y;
}
__device__ __forceinline__ float fast_log(float x) {
    float y;
    asm("lg2.approx.f32 %0, %1;" : "=f"(y) : "f"(x));
    return y * LN2;
}

// ============================ Kernel 0: decode labels + reset counter ============================
// Handles int64-on-disk (odd int32 words all zero) vs genuine int32 labels.
__global__ void decode_labels_kernel(const int* __restrict__ lab32, int n) {
    __shared__ int odd_nonzero;
    if (threadIdx.x == 0) { odd_nonzero = 0; g_done = 0u; }
    __syncthreads();
    for (int i = threadIdx.x; i < n / 2; i += blockDim.x)
        if (lab32[2 * i + 1] != 0) odd_nonzero = 1;
    __syncthreads();
    const bool is64 = (odd_nonzero == 0);
    for (int i = threadIdx.x; i < n; i += blockDim.x)
        g_lab[i] = is64 ? lab32[2 * i] : lab32[i];
}

// ============================ Kernel 1: normalize -> bf16 ============================
__global__ void normalize_kernel(const float* __restrict__ emb) {
    const int row = blockIdx.x;
    const float* in = emb + (size_t)row * DIM;

    const int c = threadIdx.x * 4;       // 128 threads * 4 = 512
    float4 x = *(const float4*)(in + c);
    float ss = x.x * x.x + x.y * x.y + x.z * x.z + x.w * x.w;

    #pragma unroll
    for (int o = 16; o; o >>= 1) ss += __shfl_xor_sync(0xffffffffu, ss, o);

    __shared__ float red[4];
    if ((threadIdx.x & 31) == 0) red[threadIdx.x >> 5] = ss;
    __syncthreads();
    const float inv = rsqrtf(red[0] + red[1] + red[2] + red[3]);

    __nv_bfloat162 p0 = __floats2bfloat162_rn(x.x * inv, x.y * inv);
    __nv_bfloat162 p1 = __floats2bfloat162_rn(x.z * inv, x.w * inv);
    __nv_bfloat162* out = (__nv_bfloat162*)(g_ebf + (size_t)row * DIM + c);
    out[0] = p0; out[1] = p1;

    if (threadIdx.x == 0) { g_num[row] = 0.0f; g_den[row] = 0.0f; }
}

// ============================ Kernel 2: mma.sync GEMM + fused epilogue + finalize ============================
__global__ __launch_bounds__(256)
void sim_loss_mma(float* __restrict__ out) {
    extern __shared__ __align__(128) char SM[];
    const uint32_t sbase = smem_u32(SM);
    const int tid = threadIdx.x, wid = tid >> 5, lane = tid & 31;
    const int wm = wid >> 2, wn = wid & 3;   // warp grid 2 (M) x 4 (N)

    // Linear block id -> upper-triangle tile (bi <= bj)
    int t = blockIdx.x, bi = 0;
    while (t >= NBLK - bi) { t -= NBLK - bi; bi++; }
    const int bj = bi + t;
    const int rowBase = bi * TM, colBase = bj * TN;
    const bool offDiag = (bi != bj);

    int*   labR = (int*)(SM + OFF_LABR);
    int*   labC = (int*)(SM + OFF_LABC);
    float* sRN  = (float*)(SM + OFF_RN);
    float* sRD  = (float*)(SM + OFF_RD);
    float* sCN  = (float*)(SM + OFF_CN);
    float* sCD  = (float*)(SM + OFF_CD);

    if (tid < 128) {
        labR[tid] = g_lab[rowBase + tid];
        labC[tid] = g_lab[colBase + tid];
        sRN[tid] = 0.0f; sRD[tid] = 0.0f;
    } else {
        sCN[tid - 128] = 0.0f; sCD[tid - 128] = 0.0f;
    }

    const __nv_bfloat16* Ag = g_ebf + (size_t)rowBase * DIM;
    const __nv_bfloat16* Bg = g_ebf + (size_t)colBase * DIM;

    // per-thread load coords (4 x 16B cp.async per chunk: 2 for A, 2 for B)
    const int ldr0 = tid >> 2,            lds0 = tid & 3;         // seg = tid
    const int ldr1 = (tid + 256) >> 2,    lds1 = tid & 3;         // seg = tid + 256

    float acc[4][4][4];
    #pragma unroll
    for (int i = 0; i < 4; i++)
        #pragma unroll
        for (int j = 0; j < 4; j++)
            #pragma unroll
            for (int v = 0; v < 4; v++) acc[i][j][v] = 0.0f;

    // ---- prologue: issue chunks 0..STAGES-2 ----
    #pragma unroll
    for (int p = 0; p < STAGES - 1; p++) {
        const int k0 = p * KC;
        const uint32_t sa = sbase + OFF_STAGE(p), sb = sa + 10240;
        CPA(sa + ldr0 * PITCH + lds0 * 16, Ag + (size_t)ldr0 * DIM + k0 + lds0 * 8);
        CPA(sb + ldr0 * PITCH + lds0 * 16, Bg + (size_t)ldr0 * DIM + k0 + lds0 * 8);
        CPA(sa + ldr1 * PITCH + lds1 * 16, Ag + (size_t)ldr1 * DIM + k0 + lds1 * 8);
        CPA(sb + ldr1 * PITCH + lds1 * 16, Bg + (size_t)ldr1 * DIM + k0 + lds1 * 8);
        CPA_COMMIT();
    }

    for (int c = 0; c < NC; c++) {
        // wait for chunk c (groups newer than c may remain pending)
        if (c < NC - 3)      CPA_WAIT(2);
        else if (c == NC - 3) CPA_WAIT(2);
        else if (c == NC - 2) CPA_WAIT(1);
        else                  CPA_WAIT(0);
        __syncthreads();

        // prefetch chunk c+STAGES-1 into buffer of chunk c-1 (safe: sync above)
        if (c + STAGES - 1 < NC) {
            const int k0 = (c + STAGES - 1) * KC;
            const int st = (c + STAGES - 1) % STAGES;
            const uint32_t sa = sbase + OFF_STAGE(st), sb = sa + 10240;
            CPA(sa + ldr0 * PITCH + lds0 * 16, Ag + (size_t)ldr0 * DIM + k0 + lds0 * 8);
            CPA(sb + ldr0 * PITCH + lds0 * 16, Bg + (size_t)ldr0 * DIM + k0 + lds0 * 8);
            CPA(sa + ldr1 * PITCH + lds1 * 16, Ag + (size_t)ldr1 * DIM + k0 + lds1 * 8);
            CPA(sb + ldr1 * PITCH + lds1 * 16, Bg + (size_t)ldr1 * DIM + k0 + lds1 * 8);
            CPA_COMMIT();
        }

        const uint32_t sa = sbase + OFF_STAGE(c % STAGES);
        const uint32_t sb = sa + 10240;

        #pragma unroll
        for (int ks = 0; ks < 2; ks++) {          // two k16 steps per 32-chunk
            uint32_t bfr[4][2];
            #pragma unroll
            for (int p = 0; p < 2; p++) {
                const int nrow = wn * 32 + p * 16 + ((lane >> 4) << 3) + (lane & 7);
                const int koff = ks * 32 + ((lane >> 3) & 1) * 16;
                uint32_t r0, r1, r2, r3;
                ldmx4(r0, r1, r2, r3, sb + nrow * PITCH + koff);
                bfr[2 * p][0] = r0; bfr[2 * p][1] = r1;
                bfr[2 * p + 1][0] = r2; bfr[2 * p + 1][1] = r3;
            }
            #pragma unroll
            for (int mt = 0; mt < 4; mt++) {
                const int arow = wm * 64 + mt * 16 + (lane & 15);
                const int akoff = ks * 32 + (lane >> 4) * 16;
                uint32_t afr[4];
                ldmx4(afr[0], afr[1], afr[2], afr[3], sa + arow * PITCH + akoff);
                #pragma unroll
                for (int nt = 0; nt < 4; nt++)
                    mma16816(acc[mt][nt], afr, bfr[nt]);
            }
        }
        // no trailing sync: next iteration's sync (after wait) protects buffer reuse
    }
    __syncthreads();   // everyone done with smem stages before accumulators get hammered

    // ---- fused epilogue (exp computed once; sign carries the v>0 predicate) ----
    #pragma unroll
    for (int mt = 0; mt < 4; mt++) {
        #pragma unroll
        for (int rh = 0; rh < 2; rh++) {
            const int rloc = wm * 64 + mt * 16 + rh * 8 + (lane >> 2);
            const int gi = rowBase + rloc;
            const int li = labR[rloc];
            float rnum = 0.0f, rden = 0.0f;
            #pragma unroll
            for (int nt = 0; nt < 4; nt++) {
                #pragma unroll
                for (int ce = 0; ce < 2; ce++) {
                    const int cloc = wn * 32 + nt * 8 + 2 * (lane & 3) + ce;
                    const int gj = colBase + cloc;
                    const float v = acc[mt][nt][rh * 2 + ce];
                    const float e = fast_exp2(v * INVT_LOG2E);
                    const bool diag = (gi == gj);
                    const bool pos = !diag && (li == labC[cloc]) && (v > 0.0f);
                    rden += diag ? 0.0f : e;
                    rnum += pos ? e : 0.0f;
                    acc[mt][nt][rh * 2 + ce] = (v > 0.0f) ? e : -e;   // cache for col pass
                }
            }
            atomicAdd(&sRD[rloc], rden);
            if (rnum != 0.0f) atomicAdd(&sRN[rloc], rnum);
        }
    }
    if (offDiag) {   // symmetric contributions to the column rows (no diag elements here)
        #pragma unroll
        for (int nt = 0; nt < 4; nt++) {
            #pragma unroll
            for (int ce = 0; ce < 2; ce++) {
                const int cloc = wn * 32 + nt * 8 + 2 * (lane & 3) + ce;
                const int lj = labC[cloc];
                float cnum = 0.0f, cden = 0.0f;
                #pragma unroll
                for (int mt = 0; mt < 4; mt++) {
                    #pragma unroll
                    for (int rh = 0; rh < 2; rh++) {
                        const int rloc = wm * 64 + mt * 16 + rh * 8 + (lane >> 2);
                        const float s = acc[mt][nt][rh * 2 + ce];
                        const float e = fabsf(s);
                        const bool pos = (labR[rloc] == lj) && (s > 0.0f);
                        cden += e;
                        cnum += pos ? e : 0.0f;
                    }
                }
                atomicAdd(&sCD[cloc], cden);
                if (cnum != 0.0f) atomicAdd(&sCN[cloc], cnum);
            }
        }
    }
    __syncthreads();

    // flush tile accumulators to global
    if (tid < 128) {
        atomicAdd(&g_den[rowBase + tid], sRD[tid]);
        const float rn = sRN[tid];
        if (rn != 0.0f) atomicAdd(&g_num[rowBase + tid], rn);
    } else if (offDiag) {
        const int i = tid - 128;
        atomicAdd(&g_den[colBase + i], sCD[i]);
        const float cn = sCN[i];
        if (cn != 0.0f) atomicAdd(&g_num[colBase + i], cn);
    }

    // ---- grid completion: last CTA computes the final loss ----
    __threadfence();
    __syncthreads();
    __shared__ int isLast;
    if (tid == 0) isLast = (atomicAdd(&g_done, 1u) == (unsigned)(gridDim.x - 1)) ? 1 : 0;
    __syncthreads();
    if (isLast) {
        float sum = 0.0f;
        int cnt = 0;
        for (int i = tid; i < NROWS; i += 256) {
            const float nu = g_num[i];
            const float de = g_den[i];
            if (nu > 0.0f && de > 0.0f) {
                sum += fast_log((de + 1e-8f) / nu);
                cnt++;
            }
        }
        #pragma unroll
        for (int o = 16; o; o >>= 1) {
            sum += __shfl_xor_sync(0xffffffffu, sum, o);
            cnt += __shfl_xor_sync(0xffffffffu, cnt, o);
        }
        float* ssum = sRN;   // reuse smem
        int*   scnt = (int*)sRD;
        if (lane == 0) { ssum[wid] = sum; scnt[wid] = cnt; }
        __syncthreads();
        if (tid == 0) {
            float s = 0.0f; int c = 0;
            #pragma unroll
            for (int i = 0; i < 8; i++) { s += ssum[i]; c += scnt[i]; }
            out[0] = (c > 0) ? fabsf(s / (float)c) : 0.0f;
        }
    }
}

extern "C" void kernel_launch(void* const* d_in, const int* in_sizes, int n_in,
                              void* d_out, int out_size) {
    const float* emb = (const float*)d_in[0];
    const int* lab32 = (const int*)d_in[1];
    float* out = (float*)d_out;

    cudaFuncSetAttribute(sim_loss_mma, cudaFuncAttributeMaxDynamicSharedMemorySize, SMEM_BYTES);

    decode_labels_kernel<<<1, 256>>>(lab32, NROWS);
    normalize_kernel<<<NROWS, 128>>>(emb);
    sim_loss_mma<<<NTILES, 256, SMEM_BYTES>>>(out);
}

// round 6
// speedup vs baseline: 6.8525x; 1.0337x over previous
#include <cuda_runtime.h>
#include <cuda_bf16.h>
#include <cstdint>

#define NROWS 8192
#define DIM   512
#define TM    128
#define TN    128
#define KC    32              // K chunk (bf16 elems): 64 B per row
#define NC    (DIM / KC)      // 16 chunks
#define NBLK  (NROWS / TM)    // 64
#define NTILES (NBLK * (NBLK + 1) / 2)   // 2080
#define PITCH 80              // smem row pitch bytes (conflict-free: 5 ⊥ 8)
#define STAGES 3
#define STAGE_BYTES 20480     // A (128*80) + B (128*80)
#define GRID 296              // 148 SMs x 2 CTAs

#define INVT_LOG2E 20.609929155556620f   // log2(e)/0.07
#define LN2 0.69314718055994531f

// ---- scratch (__device__ globals; allocation-free rule) ----
__device__ __nv_bfloat16 g_ebf[NROWS * DIM];
__device__ float g_num[NROWS];
__device__ float g_den[NROWS];
__device__ int   g_lab[NROWS];
__device__ unsigned g_done;

// ---- dynamic smem layout ----
#define OFF_RN (STAGES * STAGE_BYTES)          // 61440
#define OFF_RD (OFF_RN + 512)
#define OFF_CN (OFF_RD + 512)
#define OFF_CD (OFF_CN + 512)
#define SMEM_BYTES (OFF_CD + 512)              // 63488 -> 2 CTAs/SM

// ============================ PTX helpers ============================
__device__ __forceinline__ uint32_t smem_u32(const void* p) {
    uint32_t a;
    asm("{ .reg .u64 t; cvta.to.shared.u64 t, %1; cvt.u32.u64 %0, t; }" : "=r"(a) : "l"(p));
    return a;
}
#define CPA(dst, src)  asm volatile("cp.async.cg.shared.global [%0], [%1], 16;" :: "r"(dst), "l"(src))
#define CPA_COMMIT()   asm volatile("cp.async.commit_group;" ::: "memory")
#define CPA_WAIT(n)    asm volatile("cp.async.wait_group %0;" :: "n"(n) : "memory")

__device__ __forceinline__ void ldmx4(uint32_t& r0, uint32_t& r1, uint32_t& r2, uint32_t& r3,
                                      uint32_t addr) {
    asm volatile("ldmatrix.sync.aligned.m8n8.x4.shared.b16 {%0,%1,%2,%3}, [%4];"
                 : "=r"(r0), "=r"(r1), "=r"(r2), "=r"(r3) : "r"(addr));
}
__device__ __forceinline__ void mma16816(float* d, const uint32_t* a, const uint32_t* b) {
    asm volatile(
        "mma.sync.aligned.m16n8k16.row.col.f32.bf16.bf16.f32 "
        "{%0,%1,%2,%3}, {%4,%5,%6,%7}, {%8,%9}, {%0,%1,%2,%3};"
        : "+f"(d[0]), "+f"(d[1]), "+f"(d[2]), "+f"(d[3])
        : "r"(a[0]), "r"(a[1]), "r"(a[2]), "r"(a[3]), "r"(b[0]), "r"(b[1]));
}
__device__ __forceinline__ float fast_exp2(float x) {
    float y;
    asm("ex2.approx.f32 %0, %1;" : "=f"(y) : "f"(x));
    return y;
}
__device__ __forceinline__ float fast_log(float x) {
    float y;
    asm("lg2.approx.f32 %0, %1;" : "=f"(y) : "f"(x));
    return y * LN2;
}

// cp.async one 32-wide K chunk of A and B tiles into a stage buffer
__device__ __forceinline__ void load_chunk(uint32_t s, const __nv_bfloat16* A,
                                           const __nv_bfloat16* B, int k0, int tid) {
    const int r0 = tid >> 2, q = tid & 3;
    const int r1 = r0 + 64;
    const uint32_t sa = s, sb = s + 10240;
    CPA(sa + r0 * PITCH + q * 16, A + (size_t)r0 * DIM + k0 + q * 8);
    CPA(sb + r0 * PITCH + q * 16, B + (size_t)r0 * DIM + k0 + q * 8);
    CPA(sa + r1 * PITCH + q * 16, A + (size_t)r1 * DIM + k0 + q * 8);
    CPA(sb + r1 * PITCH + q * 16, B + (size_t)r1 * DIM + k0 + q * 8);
}

__device__ __forceinline__ void tile_coords(int t, int& bi, int& bj) {
    int b = 0;
    while (t >= NBLK - b) { t -= NBLK - b; b++; }
    bi = b; bj = b + t;
}

// ============================ Kernel 1: normalize + decode labels ============================
__global__ void normalize_kernel(const float* __restrict__ emb, const int* __restrict__ lab32) {
    const int row = blockIdx.x;
    const float* in = emb + (size_t)row * DIM;

    const int c = threadIdx.x * 4;       // 128 threads * 4 = 512
    float4 x = *(const float4*)(in + c);
    float ss = x.x * x.x + x.y * x.y + x.z * x.z + x.w * x.w;

    #pragma unroll
    for (int o = 16; o; o >>= 1) ss += __shfl_xor_sync(0xffffffffu, ss, o);

    __shared__ float red[4];
    if ((threadIdx.x & 31) == 0) red[threadIdx.x >> 5] = ss;
    __syncthreads();
    const float inv = rsqrtf(red[0] + red[1] + red[2] + red[3]);

    __nv_bfloat162 p0 = __floats2bfloat162_rn(x.x * inv, x.y * inv);
    __nv_bfloat162 p1 = __floats2bfloat162_rn(x.z * inv, x.w * inv);
    __nv_bfloat162* out = (__nv_bfloat162*)(g_ebf + (size_t)row * DIM + c);
    out[0] = p0; out[1] = p1;

    // label decode: probe 64 odd words (indices 1..127, in-bounds either layout).
    // int64 layout => all zero; genuine int32 => P(all zero) = 512^-64 ~ 0.
    if (threadIdx.x < 64) {
        const unsigned probe = __ballot_sync(0xffffffffu, lab32[2 * (threadIdx.x & 31) +
                                             ((threadIdx.x >> 5) << 6) + 1] != 0);
        if (threadIdx.x == 0) {
            // combine with the other half-warp's ballot via shared flag not needed:
            // 32 probes already give P(false) = 512^-32 ~ 1e-87
            g_lab[row] = (probe == 0u) ? lab32[2 * row] : lab32[row];
        }
    }
    if (threadIdx.x == 0) {
        g_num[row] = 0.0f; g_den[row] = 0.0f;
        if (row == 0) g_done = 0u;
    }
}

// ============================ Kernel 2: persistent mma.sync GEMM + epilogue + finalize ============================
__global__ __launch_bounds__(256, 2)
void sim_loss_mma(float* __restrict__ out) {
    extern __shared__ __align__(128) char SM[];
    const uint32_t sbase = smem_u32(SM);
    const int tid = threadIdx.x, wid = tid >> 5, lane = tid & 31;
    const int wm = wid >> 2, wn = wid & 3;   // warp grid 2 (M) x 4 (N)

    float* sRN = (float*)(SM + OFF_RN);
    float* sRD = (float*)(SM + OFF_RD);
    float* sCN = (float*)(SM + OFF_CN);
    float* sCD = (float*)(SM + OFF_CD);

    int t = blockIdx.x;
    int bi, bj;
    tile_coords(t, bi, bj);
    const __nv_bfloat16* Ag = g_ebf + (size_t)bi * TM * DIM;
    const __nv_bfloat16* Bg = g_ebf + (size_t)bj * TN * DIM;

    // prologue: chunks 0,1 of first tile
    load_chunk(sbase + 0 * STAGE_BYTES, Ag, Bg, 0, tid); CPA_COMMIT();
    load_chunk(sbase + 1 * STAGE_BYTES, Ag, Bg, KC, tid); CPA_COMMIT();
    int wbuf = 2;   // next stage to write
    int rbuf = 0;   // stage of current compute chunk

    float acc[4][4][4];
    #pragma unroll
    for (int i = 0; i < 4; i++)
        #pragma unroll
        for (int j = 0; j < 4; j++)
            #pragma unroll
            for (int v = 0; v < 4; v++) acc[i][j][v] = 0.0f;

    while (true) {
        const int rowBase = bi * TM, colBase = bj * TN;
        const bool offDiag = (bi != bj);

        // next tile (for cross-tile prefetch)
        const int tn = t + GRID;
        const bool hasNext = (tn < NTILES);
        const __nv_bfloat16 *An = Ag, *Bn = Bg;
        int nbi = bi, nbj = bj;
        if (hasNext) {
            tile_coords(tn, nbi, nbj);
            An = g_ebf + (size_t)nbi * TM * DIM;
            Bn = g_ebf + (size_t)nbj * TN * DIM;
        }

        // ---- mainloop ----
        for (int c = 0; c < NC; c++) {
            if (c == NC - 1 && !hasNext) { CPA_WAIT(0); } else { CPA_WAIT(1); }
            __syncthreads();

            const int pc = c + STAGES - 1;
            if (pc < NC) {
                load_chunk(sbase + wbuf * STAGE_BYTES, Ag, Bg, pc * KC, tid);
                CPA_COMMIT();
                wbuf = (wbuf + 1 == STAGES) ? 0 : wbuf + 1;
            } else if (hasNext && pc - NC < STAGES - 1) {
                load_chunk(sbase + wbuf * STAGE_BYTES, An, Bn, (pc - NC) * KC, tid);
                CPA_COMMIT();
                wbuf = (wbuf + 1 == STAGES) ? 0 : wbuf + 1;
            }

            const uint32_t sa = sbase + rbuf * STAGE_BYTES;
            const uint32_t sb = sa + 10240;
            rbuf = (rbuf + 1 == STAGES) ? 0 : rbuf + 1;

            #pragma unroll
            for (int ks = 0; ks < 2; ks++) {
                uint32_t bfr[4][2];
                #pragma unroll
                for (int p = 0; p < 2; p++) {
                    const int nrow = wn * 32 + p * 16 + ((lane >> 4) << 3) + (lane & 7);
                    const int koff = ks * 32 + ((lane >> 3) & 1) * 16;
                    uint32_t r0, r1, r2, r3;
                    ldmx4(r0, r1, r2, r3, sb + nrow * PITCH + koff);
                    bfr[2 * p][0] = r0; bfr[2 * p][1] = r1;
                    bfr[2 * p + 1][0] = r2; bfr[2 * p + 1][1] = r3;
                }
                #pragma unroll
                for (int mt = 0; mt < 4; mt++) {
                    const int arow = wm * 64 + mt * 16 + (lane & 15);
                    const int akoff = ks * 32 + (lane >> 4) * 16;
                    uint32_t afr[4];
                    ldmx4(afr[0], afr[1], afr[2], afr[3], sa + arow * PITCH + akoff);
                    #pragma unroll
                    for (int nt = 0; nt < 4; nt++)
                        mma16816(acc[mt][nt], afr, bfr[nt]);
                }
            }
        }

        // ---- epilogue (overlaps next-tile cp.async already in flight) ----
        __syncthreads();
        if (tid < 128) { sRN[tid] = 0.0f; sRD[tid] = 0.0f; }
        else           { sCN[tid - 128] = 0.0f; sCD[tid - 128] = 0.0f; }
        __syncthreads();

        int liArr[8], ljArr[8];
        #pragma unroll
        for (int mt = 0; mt < 4; mt++)
            #pragma unroll
            for (int rh = 0; rh < 2; rh++)
                liArr[mt * 2 + rh] = g_lab[rowBase + wm * 64 + mt * 16 + rh * 8 + (lane >> 2)];
        #pragma unroll
        for (int nt = 0; nt < 4; nt++)
            #pragma unroll
            for (int ce = 0; ce < 2; ce++)
                ljArr[nt * 2 + ce] = g_lab[colBase + wn * 32 + nt * 8 + 2 * (lane & 3) + ce];

        #pragma unroll
        for (int mt = 0; mt < 4; mt++) {
            #pragma unroll
            for (int rh = 0; rh < 2; rh++) {
                const int rloc = wm * 64 + mt * 16 + rh * 8 + (lane >> 2);
                const int gi = rowBase + rloc;
                const int li = liArr[mt * 2 + rh];
                float rnum = 0.0f, rden = 0.0f;
                #pragma unroll
                for (int nt = 0; nt < 4; nt++) {
                    #pragma unroll
                    for (int ce = 0; ce < 2; ce++) {
                        const int cloc = wn * 32 + nt * 8 + 2 * (lane & 3) + ce;
                        const int gj = colBase + cloc;
                        const float v = acc[mt][nt][rh * 2 + ce];
                        const float e = fast_exp2(v * INVT_LOG2E);
                        const bool diag = (gi == gj);
                        const bool pos = !diag && (li == ljArr[nt * 2 + ce]) && (v > 0.0f);
                        rden += diag ? 0.0f : e;
                        rnum += pos ? e : 0.0f;
                        acc[mt][nt][rh * 2 + ce] = (v > 0.0f) ? e : -e;   // cache for col pass
                    }
                }
                atomicAdd(&sRD[rloc], rden);
                if (rnum != 0.0f) atomicAdd(&sRN[rloc], rnum);
            }
        }
        if (offDiag) {
            #pragma unroll
            for (int nt = 0; nt < 4; nt++) {
                #pragma unroll
                for (int ce = 0; ce < 2; ce++) {
                    const int cloc = wn * 32 + nt * 8 + 2 * (lane & 3) + ce;
                    const int lj = ljArr[nt * 2 + ce];
                    float cnum = 0.0f, cden = 0.0f;
                    #pragma unroll
                    for (int mt = 0; mt < 4; mt++) {
                        #pragma unroll
                        for (int rh = 0; rh < 2; rh++) {
                            const float s = acc[mt][nt][rh * 2 + ce];
                            const float e = fabsf(s);
                            const bool pos = (liArr[mt * 2 + rh] == lj) && (s > 0.0f);
                            cden += e;
                            cnum += pos ? e : 0.0f;
                        }
                    }
                    atomicAdd(&sCD[cloc], cden);
                    if (cnum != 0.0f) atomicAdd(&sCN[cloc], cnum);
                }
            }
        }
        __syncthreads();

        if (tid < 128) {
            atomicAdd(&g_den[rowBase + tid], sRD[tid]);
            const float rn = sRN[tid];
            if (rn != 0.0f) atomicAdd(&g_num[rowBase + tid], rn);
        } else if (offDiag) {
            const int i = tid - 128;
            atomicAdd(&g_den[colBase + i], sCD[i]);
            const float cn = sCN[i];
            if (cn != 0.0f) atomicAdd(&g_num[colBase + i], cn);
        }

        // re-zero accumulators for next tile
        #pragma unroll
        for (int i = 0; i < 4; i++)
            #pragma unroll
            for (int j = 0; j < 4; j++)
                #pragma unroll
                for (int v = 0; v < 4; v++) acc[i][j][v] = 0.0f;

        if (!hasNext) break;
        t = tn; bi = nbi; bj = nbj; Ag = An; Bg = Bn;
    }

    // ---- grid completion: last CTA computes the final loss ----
    __syncthreads();
    __threadfence();
    __shared__ int isLast;
    if (tid == 0) isLast = (atomicAdd(&g_done, 1u) == (unsigned)(gridDim.x - 1)) ? 1 : 0;
    __syncthreads();
    if (isLast) {
        float sum = 0.0f;
        int cnt = 0;
        for (int i = tid; i < NROWS; i += 256) {
            const float nu = g_num[i];
            const float de = g_den[i];
            if (nu > 0.0f && de > 0.0f) {
                sum += fast_log((de + 1e-8f) / nu);
                cnt++;
            }
        }
        #pragma unroll
        for (int o = 16; o; o >>= 1) {
            sum += __shfl_xor_sync(0xffffffffu, sum, o);
            cnt += __shfl_xor_sync(0xffffffffu, cnt, o);
        }
        if (lane == 0) { sRN[wid] = sum; ((int*)sRD)[wid] = cnt; }
        __syncthreads();
        if (tid == 0) {
            float s = 0.0f; int c = 0;
            #pragma unroll
            for (int i = 0; i < 8; i++) { s += sRN[i]; c += ((int*)sRD)[i]; }
            out[0] = (c > 0) ? fabsf(s / (float)c) : 0.0f;
        }
    }
}

extern "C" void kernel_launch(void* const* d_in, const int* in_sizes, int n_in,
                              void* d_out, int out_size) {
    const float* emb = (const float*)d_in[0];
    const int* lab32 = (const int*)d_in[1];
    float* out = (float*)d_out;

    cudaFuncSetAttribute(sim_loss_mma, cudaFuncAttributeMaxDynamicSharedMemorySize, SMEM_BYTES);

    normalize_kernel<<<NROWS, 128>>>(emb, lab32);
    sim_loss_mma<<<GRID, 256, SMEM_BYTES>>>(out);
}

// round 9
// speedup vs baseline: 10.1225x; 1.4772x over previous
#include <cuda_runtime.h>
#include <cuda_bf16.h>
#include <cstdint>

#define NROWS 8192
#define DIM   512
#define TM    128
#define TN    128
#define KC    64              // K chunk (bf16 elems): 128 B per row
#define NC    (DIM / KC)      // 8 chunks
#define NBLK  (NROWS / TM)    // 64
#define NTILES (NBLK * (NBLK + 1) / 2)   // 2080
#define STAGES 3
#define TILE_BYTES (128 * 128)           // 16384 per operand (swizzled, no pad)
#define STAGE_BYTES (2 * TILE_BYTES)     // 32768 (A then B)
#define GRID 296              // 148 SMs x 2 CTAs

#define INVT_LOG2E 20.609929155556620f   // log2(e)/0.07
#define LN2 0.69314718055994531f

// ---- scratch (__device__ globals; allocation-free rule) ----
__device__ __nv_bfloat16 g_ebf[NROWS * DIM];
__device__ float g_num[NROWS];
__device__ float g_den[NROWS];
__device__ int   g_lab[NROWS];
__device__ unsigned g_done;

// ---- dynamic smem layout ----
#define OFF_RN (STAGES * STAGE_BYTES)          // 98304
#define OFF_RD (OFF_RN + 512)
#define OFF_CN (OFF_RD + 512)
#define OFF_CD (OFF_CN + 512)
#define SMEM_BYTES (OFF_CD + 512)              // 100352 -> 2 CTAs/SM

// swizzled smem address: row-major 128B rows, 16B seg s XOR'd with row&7
#define SWADDR(base, r, s) ((base) + ((r) << 7) + ((((s) ^ ((r) & 7))) << 4))

// ============================ PTX helpers ============================
__device__ __forceinline__ uint32_t smem_u32(const void* p) {
    uint32_t a;
    asm("{ .reg .u64 t; cvta.to.shared.u64 t, %1; cvt.u32.u64 %0, t; }" : "=r"(a) : "l"(p));
    return a;
}
#define CPA(dst, src)  asm volatile("cp.async.cg.shared.global [%0], [%1], 16;" :: "r"(dst), "l"(src))
#define CPA_COMMIT()   asm volatile("cp.async.commit_group;" ::: "memory")
#define CPA_WAIT(n)    asm volatile("cp.async.wait_group %0;" :: "n"(n) : "memory")

__device__ __forceinline__ void ldmx4(uint32_t& r0, uint32_t& r1, uint32_t& r2, uint32_t& r3,
                                      uint32_t addr) {
    asm volatile("ldmatrix.sync.aligned.m8n8.x4.shared.b16 {%0,%1,%2,%3}, [%4];"
                 : "=r"(r0), "=r"(r1), "=r"(r2), "=r"(r3) : "r"(addr));
}
__device__ __forceinline__ void mma16816(float* d, const uint32_t* a, const uint32_t* b) {
    asm volatile(
        "mma.sync.aligned.m16n8k16.row.col.f32.bf16.bf16.f32 "
        "{%0,%1,%2,%3}, {%4,%5,%6,%7}, {%8,%9}, {%0,%1,%2,%3};"
        : "+f"(d[0]), "+f"(d[1]), "+f"(d[2]), "+f"(d[3])
        : "r"(a[0]), "r"(a[1]), "r"(a[2]), "r"(a[3]), "r"(b[0]), "r"(b[1]));
}
__device__ __forceinline__ float fast_exp2(float x) {
    float y;
    asm("ex2.approx.f32 %0, %1;" : "=f"(y) : "f"(x));
    return y;
}
__device__ __forceinline__ float fast_log(float x) {
    float y;
    asm("lg2.approx.f32 %0, %1;" : "=f"(y) : "f"(x));
    return y * LN2;
}

// cp.async one 64-wide K chunk (128B/row, swizzled) of A and B into a stage buffer
__device__ __forceinline__ void load_chunk(uint32_t s, const __nv_bfloat16* A,
                                           const __nv_bfloat16* B, int k0, int tid) {
    const uint32_t sa = s, sb = s + TILE_BYTES;
    #pragma unroll
    for (int i = 0; i < 4; i++) {
        const int idx = tid + i * 256;        // 0..1023
        const int r = idx >> 3, q = idx & 7;  // row 0..127, 16B seg 0..7
        CPA(SWADDR(sa, r, q), A + (size_t)r * DIM + k0 + q * 8);
        CPA(SWADDR(sb, r, q), B + (size_t)r * DIM + k0 + q * 8);
    }
}

__device__ __forceinline__ void tile_coords(int t, int& bi, int& bj) {
    int b = 0;
    while (t >= NBLK - b) { t -= NBLK - b; b++; }
    bi = b; bj = b + t;
}

// ============================ Kernel 1: normalize + decode labels ============================
__global__ void normalize_kernel(const float* __restrict__ emb, const int* __restrict__ lab32) {
    const int row = blockIdx.x;
    const float* in = emb + (size_t)row * DIM;

    const int c = threadIdx.x * 4;
    float4 x = *(const float4*)(in + c);
    float ss = x.x * x.x + x.y * x.y + x.z * x.z + x.w * x.w;

    #pragma unroll
    for (int o = 16; o; o >>= 1) ss += __shfl_xor_sync(0xffffffffu, ss, o);

    __shared__ float red[4];
    if ((threadIdx.x & 31) == 0) red[threadIdx.x >> 5] = ss;
    __syncthreads();
    const float inv = rsqrtf(red[0] + red[1] + red[2] + red[3]);

    __nv_bfloat162 p0 = __floats2bfloat162_rn(x.x * inv, x.y * inv);
    __nv_bfloat162 p1 = __floats2bfloat162_rn(x.z * inv, x.w * inv);
    __nv_bfloat162* out = (__nv_bfloat162*)(g_ebf + (size_t)row * DIM + c);
    out[0] = p0; out[1] = p1;

    // label decode: 32 odd-word probes (in-bounds under either layout).
    // int64 layout => all zero; int32 => P(all zero) = 512^-32 ~ 0.
    if (threadIdx.x < 32) {
        const unsigned probe = __ballot_sync(0xffffffffu, lab32[2 * threadIdx.x + 1] != 0);
        if (threadIdx.x == 0)
            g_lab[row] = (probe == 0u) ? lab32[2 * row] : lab32[row];
    }
    if (threadIdx.x == 0) {
        g_num[row] = 0.0f; g_den[row] = 0.0f;
        if (row == 0) g_done = 0u;
    }
}

// ============================ Kernel 2: persistent mma.sync GEMM + epilogue + finalize ============================
__global__ __launch_bounds__(256, 2)
void sim_loss_mma(float* __restrict__ out) {
    extern __shared__ __align__(128) char SM[];
    const uint32_t sbase = smem_u32(SM);
    const int tid = threadIdx.x, wid = tid >> 5, lane = tid & 31;
    const int wm = wid >> 2, wn = wid & 3;   // warp grid 2 (M) x 4 (N)

    float* sRN = (float*)(SM + OFF_RN);
    float* sRD = (float*)(SM + OFF_RD);
    float* sCN = (float*)(SM + OFF_CN);
    float* sCD = (float*)(SM + OFF_CD);

    int t = blockIdx.x;
    int bi, bj;
    tile_coords(t, bi, bj);
    const __nv_bfloat16* Ag = g_ebf + (size_t)bi * TM * DIM;
    const __nv_bfloat16* Bg = g_ebf + (size_t)bj * TN * DIM;

    // prologue: chunks 0,1 of first tile into buffers 0,1
    load_chunk(sbase + 0 * STAGE_BYTES, Ag, Bg, 0, tid); CPA_COMMIT();
    load_chunk(sbase + 1 * STAGE_BYTES, Ag, Bg, KC, tid); CPA_COMMIT();
    int wbuf = 2;   // next buffer to write (cycles 0..2 across tiles)
    int rbuf = 0;   // buffer of current compute chunk

    float acc[4][4][4];
    #pragma unroll
    for (int i = 0; i < 4; i++)
        #pragma unroll
        for (int j = 0; j < 4; j++)
            #pragma unroll
            for (int v = 0; v < 4; v++) acc[i][j][v] = 0.0f;

    while (true) {
        const int rowBase = bi * TM, colBase = bj * TN;
        const bool offDiag = (bi != bj);

        const int tn = t + GRID;
        const bool hasNext = (tn < NTILES);
        const __nv_bfloat16 *An = Ag, *Bn = Bg;
        int nbi = bi, nbj = bj;
        if (hasNext) {
            tile_coords(tn, nbi, nbj);
            An = g_ebf + (size_t)nbi * TM * DIM;
            Bn = g_ebf + (size_t)nbj * TN * DIM;
        }

        // ---- mainloop: 8 chunks of K=64, 3-stage cycle, prefetch distance 2 ----
        #pragma unroll 1
        for (int c = 0; c < NC; c++) {
            // pending groups before wait: {c, c+1} steady-state
            if (c == NC - 1 && !hasNext) { CPA_WAIT(0); } else { CPA_WAIT(1); }
            __syncthreads();   // also guarantees buffer (c-1)'s reads are complete

            // prefetch chunk c+2 into the buffer consumed at iteration c-1
            const int pc = c + STAGES - 1;   // c + 2
            if (pc < NC) {
                load_chunk(sbase + wbuf * STAGE_BYTES, Ag, Bg, pc * KC, tid);
                CPA_COMMIT();
                wbuf = (wbuf + 1 == STAGES) ? 0 : wbuf + 1;
            } else if (hasNext && pc - NC < STAGES - 1) {
                load_chunk(sbase + wbuf * STAGE_BYTES, An, Bn, (pc - NC) * KC, tid);
                CPA_COMMIT();
                wbuf = (wbuf + 1 == STAGES) ? 0 : wbuf + 1;
            }

            const uint32_t sa = sbase + rbuf * STAGE_BYTES;
            const uint32_t sb = sa + TILE_BYTES;
            rbuf = (rbuf + 1 == STAGES) ? 0 : rbuf + 1;

            #pragma unroll
            for (int ks = 0; ks < 4; ks++) {          // four k16 steps per 64-chunk
                uint32_t bfr[4][2];
                #pragma unroll
                for (int p = 0; p < 2; p++) {
                    const int nrow = wn * 32 + p * 16 + ((lane >> 4) << 3) + (lane & 7);
                    const int seg = ks * 2 + ((lane >> 3) & 1);
                    uint32_t r0, r1, r2, r3;
                    ldmx4(r0, r1, r2, r3, SWADDR(sb, nrow, seg));
                    bfr[2 * p][0] = r0; bfr[2 * p][1] = r1;
                    bfr[2 * p + 1][0] = r2; bfr[2 * p + 1][1] = r3;
                }
                #pragma unroll
                for (int mt = 0; mt < 4; mt++) {
                    const int arow = wm * 64 + mt * 16 + (lane & 15);
                    const int aseg = ks * 2 + (lane >> 4);
                    uint32_t afr[4];
                    ldmx4(afr[0], afr[1], afr[2], afr[3], SWADDR(sa, arow, aseg));
                    #pragma unroll
                    for (int nt = 0; nt < 4; nt++)
                        mma16816(acc[mt][nt], afr, bfr[nt]);
                }
            }
        }

        // ---- epilogue (next-tile chunks 0,1 already in flight) ----
        __syncthreads();
        if (tid < 128) { sRN[tid] = 0.0f; sRD[tid] = 0.0f; }
        else           { sCN[tid - 128] = 0.0f; sCD[tid - 128] = 0.0f; }
        __syncthreads();

        int liArr[8], ljArr[8];
        #pragma unroll
        for (int mt = 0; mt < 4; mt++)
            #pragma unroll
            for (int rh = 0; rh < 2; rh++)
                liArr[mt * 2 + rh] = g_lab[rowBase + wm * 64 + mt * 16 + rh * 8 + (lane >> 2)];
        #pragma unroll
        for (int nt = 0; nt < 4; nt++)
            #pragma unroll
            for (int ce = 0; ce < 2; ce++)
                ljArr[nt * 2 + ce] = g_lab[colBase + wn * 32 + nt * 8 + 2 * (lane & 3) + ce];

        // row pass: exp once; sign carries the v>0 predicate for the col pass
        #pragma unroll
        for (int mt = 0; mt < 4; mt++) {
            #pragma unroll
            for (int rh = 0; rh < 2; rh++) {
                const int rloc = wm * 64 + mt * 16 + rh * 8 + (lane >> 2);
                const int gi = rowBase + rloc;
                const int li = liArr[mt * 2 + rh];
                float rnum = 0.0f, rden = 0.0f;
                #pragma unroll
                for (int nt = 0; nt < 4; nt++) {
                    #pragma unroll
                    for (int ce = 0; ce < 2; ce++) {
                        const int cloc = wn * 32 + nt * 8 + 2 * (lane & 3) + ce;
                        const int gj = colBase + cloc;
                        const float v = acc[mt][nt][rh * 2 + ce];
                        const float e = fast_exp2(v * INVT_LOG2E);
                        const bool diag = (gi == gj);
                        const bool pos = !diag && (li == ljArr[nt * 2 + ce]) && (v > 0.0f);
                        rden += diag ? 0.0f : e;
                        rnum += pos ? e : 0.0f;
                        acc[mt][nt][rh * 2 + ce] = (v > 0.0f) ? e : -e;
                    }
                }
                // quad reduce (lanes sharing rloc differ in lane bits 0-1)
                rnum += __shfl_xor_sync(0xffffffffu, rnum, 1);
                rden += __shfl_xor_sync(0xffffffffu, rden, 1);
                rnum += __shfl_xor_sync(0xffffffffu, rnum, 2);
                rden += __shfl_xor_sync(0xffffffffu, rden, 2);
                if ((lane & 3) == 0) {
                    atomicAdd(&sRD[rloc], rden);
                    if (rnum != 0.0f) atomicAdd(&sRN[rloc], rnum);
                }
            }
        }
        if (offDiag) {
            #pragma unroll
            for (int nt = 0; nt < 4; nt++) {
                #pragma unroll
                for (int ce = 0; ce < 2; ce++) {
                    const int cloc = wn * 32 + nt * 8 + 2 * (lane & 3) + ce;
                    const int lj = ljArr[nt * 2 + ce];
                    float cnum = 0.0f, cden = 0.0f;
                    #pragma unroll
                    for (int mt = 0; mt < 4; mt++) {
                        #pragma unroll
                        for (int rh = 0; rh < 2; rh++) {
                            const float s = acc[mt][nt][rh * 2 + ce];
                            const float e = fabsf(s);
                            const bool pos = (liArr[mt * 2 + rh] == lj) && (s > 0.0f);
                            cden += e;
                            cnum += pos ? e : 0.0f;
                        }
                    }
                    // reduce over lane bits 2-4 (8 lanes share each cloc)
                    cnum += __shfl_xor_sync(0xffffffffu, cnum, 4);
                    cden += __shfl_xor_sync(0xffffffffu, cden, 4);
                    cnum += __shfl_xor_sync(0xffffffffu, cnum, 8);
                    cden += __shfl_xor_sync(0xffffffffu, cden, 8);
                    cnum += __shfl_xor_sync(0xffffffffu, cnum, 16);
                    cden += __shfl_xor_sync(0xffffffffu, cden, 16);
                    if (lane < 4) {   // one writer per lane&3 group
                        atomicAdd(&sCD[cloc], cden);
                        if (cnum != 0.0f) atomicAdd(&sCN[cloc], cnum);
                    }
                }
            }
        }
        __syncthreads();

        if (tid < 128) {
            atomicAdd(&g_den[rowBase + tid], sRD[tid]);
            const float rn = sRN[tid];
            if (rn != 0.0f) atomicAdd(&g_num[rowBase + tid], rn);
        } else if (offDiag) {
            const int i = tid - 128;
            atomicAdd(&g_den[colBase + i], sCD[i]);
            const float cn = sCN[i];
            if (cn != 0.0f) atomicAdd(&g_num[colBase + i], cn);
        }

        #pragma unroll
        for (int i = 0; i < 4; i++)
            #pragma unroll
            for (int j = 0; j < 4; j++)
                #pragma unroll
                for (int v = 0; v < 4; v++) acc[i][j][v] = 0.0f;

        if (!hasNext) break;
        t = tn; bi = nbi; bj = nbj; Ag = An; Bg = Bn;
    }

    // ---- grid completion: last CTA computes the final loss ----
    __syncthreads();
    __threadfence();
    __shared__ int isLast;
    if (tid == 0) isLast = (atomicAdd(&g_done, 1u) == (unsigned)(gridDim.x - 1)) ? 1 : 0;
    __syncthreads();
    if (isLast) {
        float sum = 0.0f;
        int cnt = 0;
        for (int i = tid; i < NROWS; i += 256) {
            const float nu = g_num[i];
            const float de = g_den[i];
            if (nu > 0.0f && de > 0.0f) {
                sum += fast_log((de + 1e-8f) / nu);
                cnt++;
            }
        }
        #pragma unroll
        for (int o = 16; o; o >>= 1) {
            sum += __shfl_xor_sync(0xffffffffu, sum, o);
            cnt += __shfl_xor_sync(0xffffffffu, cnt, o);
        }
        if (lane == 0) { sRN[wid] = sum; ((int*)sRD)[wid] = cnt; }
        __syncthreads();
        if (tid == 0) {
            float s = 0.0f; int c = 0;
            #pragma unroll
            for (int i = 0; i < 8; i++) { s += sRN[i]; c += ((int*)sRD)[i]; }
            out[0] = (c > 0) ? fabsf(s / (float)c) : 0.0f;
        }
    }
}

extern "C" void kernel_launch(void* const* d_in, const int* in_sizes, int n_in,
                              void* d_out, int out_size) {
    const float* emb = (const float*)d_in[0];
    const int* lab32 = (const int*)d_in[1];
    float* out = (float*)d_out;

    cudaFuncSetAttribute(sim_loss_mma, cudaFuncAttributeMaxDynamicSharedMemorySize, SMEM_BYTES);

    normalize_kernel<<<NROWS, 128>>>(emb, lab32);
    sim_loss_mma<<<GRID, 256, SMEM_BYTES>>>(out);
}